// round 1
// baseline (speedup 1.0000x reference)
#include <cuda_runtime.h>

// ---------------- problem constants ----------------
constexpr int N_  = 20000;
constexpr int E_  = 200000;
constexpr int H_  = 4;
constexpr int C_  = 64;
constexpr int G_  = 64;
constexpr int NC_ = 751;
constexpr int HC_ = H_ * C_;       // 256
constexpr int ET_ = E_ + N_;       // edges incl self loops

// ---------------- scratch (device globals; no allocation allowed) ----------------
__device__ float    d_xl1[(size_t)N_ * HC_];
__device__ float    d_xr1[(size_t)N_ * HC_];
__device__ float    d_ep1[(size_t)E_ * HC_];     // edge_attr @ W1e
__device__ float    d_ep2[(size_t)E_ * C_];      // edge_attr @ W2e
__device__ float    d_lep1[(size_t)N_ * HC_];    // self-loop projected attr (layer1)
__device__ float    d_lep2[(size_t)N_ * C_];
__device__ int      d_cnt[N_];
__device__ float    d_logit1[(size_t)ET_ * H_];
__device__ float    d_logit2[ET_];
__device__ unsigned d_lmax1[N_ * H_];
__device__ unsigned d_lmax2[N_];
__device__ float    d_den1[N_ * H_];
__device__ float    d_den2[N_];
__device__ float    d_h1[(size_t)N_ * HC_];      // layer1 accum -> h1
__device__ float    d_h2[(size_t)N_ * C_];       // layer2 accum -> h2
__device__ float    d_xl2[(size_t)N_ * C_];
__device__ float    d_xr2[(size_t)N_ * C_];
__device__ unsigned d_gmax[G_ * C_];

// ---------------- helpers ----------------
__device__ __forceinline__ unsigned fenc(float f) {
    unsigned u = __float_as_uint(f);
    return (u & 0x80000000u) ? ~u : (u | 0x80000000u);
}
__device__ __forceinline__ float fdec(unsigned u) {
    u = (u & 0x80000000u) ? (u & 0x7fffffffu) : ~u;
    return __uint_as_float(u);
}
constexpr unsigned ENC_NEG_INF = 0x007fffffu;   // fenc(-inf)

__device__ __forceinline__ unsigned long long pk2(float x, float y) {
    unsigned long long r;
    asm("mov.b64 %0, {%1, %2};" : "=l"(r) : "f"(x), "f"(y));
    return r;
}
__device__ __forceinline__ void unpk2(unsigned long long v, float& lo, float& hi) {
    asm("mov.b64 {%0, %1}, %2;" : "=f"(lo), "=f"(hi) : "l"(v));
}
__device__ __forceinline__ void fma2(unsigned long long& c, unsigned long long a, unsigned long long b) {
    asm("fma.rn.f32x2 %0, %1, %2, %0;" : "+l"(c) : "l"(a), "l"(b));
}

// ---------------- init ----------------
__global__ void init_kernel() {
    int i0 = blockIdx.x * blockDim.x + threadIdx.x;
    int stride = gridDim.x * blockDim.x;
    for (int i = i0; i < N_ * HC_; i += stride) { d_h1[i] = 0.f; d_lep1[i] = 0.f; }
    for (int i = i0; i < N_ * C_;  i += stride) { d_h2[i] = 0.f; d_lep2[i] = 0.f; }
    for (int i = i0; i < N_ * H_;  i += stride) { d_den1[i] = 0.f; d_lmax1[i] = ENC_NEG_INF; }
    for (int i = i0; i < N_;       i += stride) { d_den2[i] = 0.f; d_lmax2[i] = ENC_NEG_INF; d_cnt[i] = 0; }
    for (int i = i0; i < G_ * C_;  i += stride) { d_gmax[i] = ENC_NEG_INF; }
}

__global__ void cnt_kernel(const int* __restrict__ col) {
    int e = blockIdx.x * blockDim.x + threadIdx.x;
    if (e < E_) atomicAdd(&d_cnt[col[e]], 1);
}

// ---------------- SGEMM: C = A(MxK) @ B(KxNn) [+bias], fp32 with packed f32x2 FMA ----------------
// BM=128, BN=64, BK=16, 256 threads, per-thread 8(M)x4(N) via 4x4 f32x2 accumulators.
__global__ __launch_bounds__(256) void sgemm_kernel(
    const float* __restrict__ A, const float* __restrict__ B,
    const float* __restrict__ bias, float* __restrict__ Cm,
    int M, int K, int Nn)
{
    constexpr int BM = 128, BN = 64, BK = 16;
    __shared__ float As[BK][132];   // k-major (transposed), padded
    __shared__ float Bs[BK][BN];

    const int bm = blockIdx.x * BM;
    const int bn = blockIdx.y * BN;
    const int tid = threadIdx.x;
    const int ty = tid >> 4;        // 0..15 (M)
    const int tx = tid & 15;        // 0..15 (N)

    unsigned long long acc[4][4];
    #pragma unroll
    for (int m = 0; m < 4; m++)
        #pragma unroll
        for (int n = 0; n < 4; n++) acc[m][n] = 0ull;

    for (int k0 = 0; k0 < K; k0 += BK) {
        // load A tile (128x16), store transposed
        #pragma unroll
        for (int l = 0; l < 2; l++) {
            int idx = tid + l * 256;            // 0..511 float4s
            int r = idx >> 2;
            int kk = (idx & 3) * 4;
            float4 v = make_float4(0.f, 0.f, 0.f, 0.f);
            int gr = bm + r;
            if (gr < M) v = *(const float4*)&A[(size_t)gr * K + k0 + kk];
            As[kk + 0][r] = v.x; As[kk + 1][r] = v.y; As[kk + 2][r] = v.z; As[kk + 3][r] = v.w;
        }
        // load B tile (16x64)
        {
            int kb = tid >> 4;
            int cb = (tid & 15) * 4;
            float4 v = *(const float4*)&B[(size_t)(k0 + kb) * Nn + bn + cb];
            *(float4*)&Bs[kb][cb] = v;
        }
        __syncthreads();

        #pragma unroll
        for (int k = 0; k < BK; k++) {
            ulonglong2 t1 = *(const ulonglong2*)&As[k][ty * 8];
            ulonglong2 t2 = *(const ulonglong2*)&As[k][ty * 8 + 4];
            unsigned long long ap[4] = { t1.x, t1.y, t2.x, t2.y };
            float4 b = *(const float4*)&Bs[k][tx * 4];
            unsigned long long bd[4];
            bd[0] = pk2(b.x, b.x); bd[1] = pk2(b.y, b.y);
            bd[2] = pk2(b.z, b.z); bd[3] = pk2(b.w, b.w);
            #pragma unroll
            for (int m = 0; m < 4; m++)
                #pragma unroll
                for (int n = 0; n < 4; n++)
                    fma2(acc[m][n], ap[m], bd[n]);
        }
        __syncthreads();
    }

    float bv[4] = {0.f, 0.f, 0.f, 0.f};
    if (bias) {
        #pragma unroll
        for (int n = 0; n < 4; n++) bv[n] = bias[bn + tx * 4 + n];
    }
    #pragma unroll
    for (int m = 0; m < 4; m++) {
        float lo[4], hi[4];
        #pragma unroll
        for (int n = 0; n < 4; n++) unpk2(acc[m][n], lo[n], hi[n]);
        int r0 = bm + ty * 8 + 2 * m;
        int r1 = r0 + 1;
        if (r0 < M) {
            float4 o = make_float4(lo[0] + bv[0], lo[1] + bv[1], lo[2] + bv[2], lo[3] + bv[3]);
            *(float4*)&Cm[(size_t)r0 * Nn + bn + tx * 4] = o;
        }
        if (r1 < M) {
            float4 o = make_float4(hi[0] + bv[0], hi[1] + bv[1], hi[2] + bv[2], hi[3] + bv[3]);
            *(float4*)&Cm[(size_t)r1 * Nn + bn + tx * 4] = o;
        }
    }
}

// ---------------- self-loop attr projection: scatter + divide ----------------
__global__ void scatter_loop_kernel(const int* __restrict__ col) {
    int e = blockIdx.x;
    int r = threadIdx.x;              // 0..319
    int c = col[e];
    if (r < HC_) atomicAdd(&d_lep1[(size_t)c * HC_ + r], d_ep1[(size_t)e * HC_ + r]);
    else         atomicAdd(&d_lep2[(size_t)c * C_ + (r - HC_)], d_ep2[(size_t)e * C_ + (r - HC_)]);
}

__global__ void div_loop_kernel() {
    int n = blockIdx.x;
    int r = threadIdx.x;
    float inv = 1.0f / (float)max(d_cnt[n], 1);
    if (r < HC_) d_lep1[(size_t)n * HC_ + r] *= inv;
    else         d_lep2[(size_t)n * C_ + (r - HC_)] *= inv;
}

// ---------------- layer 1 attention ----------------
// warp per edge; lane handles 8 channels (lanes [8h,8h+8) -> head h)
__global__ void attA1_kernel(const int* __restrict__ row, const int* __restrict__ col,
                             const float* __restrict__ att) {
    int w = (blockIdx.x * blockDim.x + threadIdx.x) >> 5;
    int lane = threadIdx.x & 31;
    if (w >= ET_) return;
    int i, j; const float* ep;
    if (w < E_) { i = row[w]; j = col[w]; ep = d_ep1 + (size_t)w * HC_; }
    else        { i = j = w - E_;         ep = d_lep1 + (size_t)(w - E_) * HC_; }

    const float4* xl4 = (const float4*)(d_xl1 + (size_t)j * HC_) + lane * 2;
    const float4* xr4 = (const float4*)(d_xr1 + (size_t)i * HC_) + lane * 2;
    const float4* ep4 = (const float4*)ep + lane * 2;
    const float4* at4 = (const float4*)att + lane * 2;

    float s = 0.f;
    #pragma unroll
    for (int q = 0; q < 2; q++) {
        float4 a = xl4[q], b = xr4[q], e4 = ep4[q], t = at4[q];
        float v;
        v = a.x + b.x + e4.x; v = v > 0.f ? v : 0.2f * v; s += v * t.x;
        v = a.y + b.y + e4.y; v = v > 0.f ? v : 0.2f * v; s += v * t.y;
        v = a.z + b.z + e4.z; v = v > 0.f ? v : 0.2f * v; s += v * t.z;
        v = a.w + b.w + e4.w; v = v > 0.f ? v : 0.2f * v; s += v * t.w;
    }
    s += __shfl_xor_sync(0xffffffffu, s, 1);
    s += __shfl_xor_sync(0xffffffffu, s, 2);
    s += __shfl_xor_sync(0xffffffffu, s, 4);
    if ((lane & 7) == 0) {
        int h = lane >> 3;
        d_logit1[(size_t)w * H_ + h] = s;
        atomicMax(&d_lmax1[i * H_ + h], fenc(s));
    }
}

__global__ void attB1_kernel(const int* __restrict__ row, const int* __restrict__ col) {
    int w = (blockIdx.x * blockDim.x + threadIdx.x) >> 5;
    int lane = threadIdx.x & 31;
    if (w >= ET_) return;
    int i, j;
    if (w < E_) { i = row[w]; j = col[w]; }
    else        { i = j = w - E_; }
    int h = lane >> 3;
    float m = fdec(d_lmax1[i * H_ + h]);
    float ex = __expf(d_logit1[(size_t)w * H_ + h] - m);
    if ((lane & 7) == 0) atomicAdd(&d_den1[i * H_ + h], ex);

    const float4* xl4 = (const float4*)(d_xl1 + (size_t)j * HC_) + lane * 2;
    float* op = d_h1 + (size_t)i * HC_ + lane * 8;
    float4 a = xl4[0], b = xl4[1];
    atomicAdd(op + 0, a.x * ex); atomicAdd(op + 1, a.y * ex);
    atomicAdd(op + 2, a.z * ex); atomicAdd(op + 3, a.w * ex);
    atomicAdd(op + 4, b.x * ex); atomicAdd(op + 5, b.y * ex);
    atomicAdd(op + 6, b.z * ex); atomicAdd(op + 7, b.w * ex);
}

__global__ void finC1_kernel(const float* __restrict__ bias) {
    int idx = blockIdx.x * blockDim.x + threadIdx.x;
    if (idx >= N_ * HC_) return;
    int k = idx & (HC_ - 1);
    int node = idx >> 8;
    int h = k >> 6;
    float v = d_h1[idx] / d_den1[node * H_ + h] + bias[k];
    d_h1[idx] = v > 0.f ? v : 0.01f * v;
}

// ---------------- layer 2 attention (H=1, C=64): warp per edge, lane -> 2 channels ----------------
__global__ void attA2_kernel(const int* __restrict__ row, const int* __restrict__ col,
                             const float* __restrict__ att) {
    int w = (blockIdx.x * blockDim.x + threadIdx.x) >> 5;
    int lane = threadIdx.x & 31;
    if (w >= ET_) return;
    int i, j; const float* ep;
    if (w < E_) { i = row[w]; j = col[w]; ep = d_ep2 + (size_t)w * C_; }
    else        { i = j = w - E_;         ep = d_lep2 + (size_t)(w - E_) * C_; }

    float2 a = ((const float2*)(d_xl2 + (size_t)j * C_))[lane];
    float2 b = ((const float2*)(d_xr2 + (size_t)i * C_))[lane];
    float2 e2 = ((const float2*)ep)[lane];
    float2 t = ((const float2*)att)[lane];
    float v0 = a.x + b.x + e2.x; v0 = v0 > 0.f ? v0 : 0.2f * v0;
    float v1 = a.y + b.y + e2.y; v1 = v1 > 0.f ? v1 : 0.2f * v1;
    float s = v0 * t.x + v1 * t.y;
    #pragma unroll
    for (int o = 1; o < 32; o <<= 1) s += __shfl_xor_sync(0xffffffffu, s, o);
    if (lane == 0) {
        d_logit2[w] = s;
        atomicMax(&d_lmax2[i], fenc(s));
    }
}

__global__ void attB2_kernel(const int* __restrict__ row, const int* __restrict__ col) {
    int w = (blockIdx.x * blockDim.x + threadIdx.x) >> 5;
    int lane = threadIdx.x & 31;
    if (w >= ET_) return;
    int i, j;
    if (w < E_) { i = row[w]; j = col[w]; }
    else        { i = j = w - E_; }
    float m = fdec(d_lmax2[i]);
    float ex = __expf(d_logit2[w] - m);
    if (lane == 0) atomicAdd(&d_den2[i], ex);
    float2 a = ((const float2*)(d_xl2 + (size_t)j * C_))[lane];
    float* op = d_h2 + (size_t)i * C_ + lane * 2;
    atomicAdd(op + 0, a.x * ex);
    atomicAdd(op + 1, a.y * ex);
}

__global__ void finC2_kernel(const float* __restrict__ bias) {
    int idx = blockIdx.x * blockDim.x + threadIdx.x;
    if (idx >= N_ * C_) return;
    float v = d_h2[idx] / d_den2[idx >> 6] + bias[idx & 63];
    d_h2[idx] = v > 0.f ? v : 0.01f * v;
}

// ---------------- global max pool ----------------
__global__ void pool_kernel(const int* __restrict__ batch) {
    int idx = blockIdx.x * blockDim.x + threadIdx.x;
    if (idx >= N_ * C_) return;
    int n = idx >> 6;
    int c = idx & 63;
    atomicMax(&d_gmax[batch[n] * C_ + c], fenc(d_h2[idx]));
}

// ---------------- layernorm + classifier ----------------
__global__ void final_kernel(const float* __restrict__ ln_g, const float* __restrict__ ln_b,
                             const float* __restrict__ clf_W, const float* __restrict__ clf_b,
                             float* __restrict__ out, int out_size) {
    int g = blockIdx.x;
    int tid = threadIdx.x;
    __shared__ float sg[C_];
    __shared__ float sgn[C_];
    __shared__ float s_mu, s_rstd;
    if (tid < C_) sg[tid] = fdec(d_gmax[g * C_ + tid]);
    __syncthreads();
    if (tid == 0) {
        float m = 0.f;
        for (int c = 0; c < C_; c++) m += sg[c];
        m *= (1.0f / C_);
        float v = 0.f;
        for (int c = 0; c < C_; c++) { float d = sg[c] - m; v += d * d; }
        v *= (1.0f / C_);
        s_mu = m;
        s_rstd = rsqrtf(v + 1e-5f);
    }
    __syncthreads();
    if (tid < C_) {
        float gn = (sg[tid] - s_mu) * s_rstd * ln_g[tid] + ln_b[tid];
        sgn[tid] = gn;
        if (out_size >= G_ * NC_ + G_ * C_) out[G_ * NC_ + g * C_ + tid] = gn;
    }
    __syncthreads();
    for (int o = tid; o < NC_; o += blockDim.x) {
        float s = clf_b[o];
        #pragma unroll 8
        for (int c = 0; c < C_; c++) s += sgn[c] * clf_W[c * NC_ + o];
        out[g * NC_ + o] = s;
    }
}

// ---------------- launch ----------------
extern "C" void kernel_launch(void* const* d_in, const int* in_sizes, int n_in,
                              void* d_out, int out_size) {
    const float* x     = (const float*)d_in[0];
    const int*   ei    = (const int*)  d_in[1];
    const float* ea    = (const float*)d_in[2];
    const int*   batch = (const int*)  d_in[3];
    const float* W1l = (const float*)d_in[4];  const float* b1l  = (const float*)d_in[5];
    const float* W1r = (const float*)d_in[6];  const float* b1r  = (const float*)d_in[7];
    const float* W1e = (const float*)d_in[8];  const float* att1 = (const float*)d_in[9];
    const float* bias1 = (const float*)d_in[10];
    const float* W2l = (const float*)d_in[11]; const float* b2l  = (const float*)d_in[12];
    const float* W2r = (const float*)d_in[13]; const float* b2r  = (const float*)d_in[14];
    const float* W2e = (const float*)d_in[15]; const float* att2 = (const float*)d_in[16];
    const float* bias2 = (const float*)d_in[17];
    const float* ln_g = (const float*)d_in[18]; const float* ln_b = (const float*)d_in[19];
    const float* clfW = (const float*)d_in[20]; const float* clfb = (const float*)d_in[21];

    const int* row = ei;
    const int* col = ei + E_;
    float* out = (float*)d_out;

    float *p_xl1, *p_xr1, *p_ep1, *p_ep2, *p_h1, *p_xl2, *p_xr2;
    cudaGetSymbolAddress((void**)&p_xl1, d_xl1);
    cudaGetSymbolAddress((void**)&p_xr1, d_xr1);
    cudaGetSymbolAddress((void**)&p_ep1, d_ep1);
    cudaGetSymbolAddress((void**)&p_ep2, d_ep2);
    cudaGetSymbolAddress((void**)&p_h1,  d_h1);
    cudaGetSymbolAddress((void**)&p_xl2, d_xl2);
    cudaGetSymbolAddress((void**)&p_xr2, d_xr2);

    init_kernel<<<4096, 256>>>();
    cnt_kernel<<<(E_ + 255) / 256, 256>>>(col);

    // GEMMs
    {
        dim3 gE((E_ + 127) / 128, HC_ / 64);
        sgemm_kernel<<<gE, 256>>>(ea, W1e, nullptr, p_ep1, E_, 384, HC_);
        dim3 gE2((E_ + 127) / 128, 1);
        sgemm_kernel<<<gE2, 256>>>(ea, W2e, nullptr, p_ep2, E_, 384, C_);
        dim3 gX((N_ + 127) / 128, HC_ / 64);
        sgemm_kernel<<<gX, 256>>>(x, W1l, b1l, p_xl1, N_, 512, HC_);
        sgemm_kernel<<<gX, 256>>>(x, W1r, b1r, p_xr1, N_, 512, HC_);
    }

    scatter_loop_kernel<<<E_, 320>>>(col);
    div_loop_kernel<<<N_, 320>>>();

    // layer 1
    int attBlocks = (ET_ * 32 + 255) / 256;
    attA1_kernel<<<attBlocks, 256>>>(row, col, att1);
    attB1_kernel<<<attBlocks, 256>>>(row, col);
    finC1_kernel<<<(N_ * HC_ + 255) / 256, 256>>>(bias1);

    // layer 2 transforms
    {
        dim3 gH((N_ + 127) / 128, 1);
        sgemm_kernel<<<gH, 256>>>(p_h1, W2l, b2l, p_xl2, N_, HC_, C_);
        sgemm_kernel<<<gH, 256>>>(p_h1, W2r, b2r, p_xr2, N_, HC_, C_);
    }

    attA2_kernel<<<attBlocks, 256>>>(row, col, att2);
    attB2_kernel<<<attBlocks, 256>>>(row, col);
    finC2_kernel<<<(N_ * C_ + 255) / 256, 256>>>(bias2);

    pool_kernel<<<(N_ * C_ + 255) / 256, 256>>>(batch);
    final_kernel<<<G_, 256>>>(ln_g, ln_b, clfW, clfb, out, out_size);
}

// round 2
// speedup vs baseline: 1.1609x; 1.1609x over previous
#include <cuda_runtime.h>
#include <math_constants.h>

// ---------------- problem constants ----------------
constexpr int N_  = 20000;
constexpr int E_  = 200000;
constexpr int H_  = 4;
constexpr int C_  = 64;
constexpr int G_  = 64;
constexpr int NC_ = 751;
constexpr int HC_ = H_ * C_;       // 256

// ---------------- scratch (device globals; no allocation allowed) ----------------
__device__ float    d_xl1[(size_t)N_ * HC_];
__device__ float    d_xr1[(size_t)N_ * HC_];
__device__ float    d_ep1[(size_t)E_ * HC_];     // edge_attr @ W1e
__device__ float    d_ep2[(size_t)E_ * C_];      // edge_attr @ W2e
__device__ float    d_lep1[(size_t)N_ * HC_];    // self-loop projected attr (layer1)
__device__ float    d_lep2[(size_t)N_ * C_];
__device__ float    d_h1[(size_t)N_ * HC_];
__device__ float    d_h2[(size_t)N_ * C_];
__device__ float    d_xl2[(size_t)N_ * C_];
__device__ float    d_xr2[(size_t)N_ * C_];
__device__ unsigned d_gmax[G_ * C_];

// CSR structures
__device__ int d_cnt_row[N_], d_cnt_col[N_];
__device__ int d_rowptr[N_ + 1], d_colptr[N_ + 1];
__device__ int d_rowcur[N_], d_colcur[N_];
__device__ int d_rowe[E_];     // edge id sorted by row (target i)
__device__ int d_rowj[E_];     // col[e] for same ordering (source j)
__device__ int d_cole[E_];     // edge id sorted by col

// ---------------- helpers ----------------
__device__ __forceinline__ unsigned fenc(float f) {
    unsigned u = __float_as_uint(f);
    return (u & 0x80000000u) ? ~u : (u | 0x80000000u);
}
__device__ __forceinline__ float fdec(unsigned u) {
    u = (u & 0x80000000u) ? (u & 0x7fffffffu) : ~u;
    return __uint_as_float(u);
}
constexpr unsigned ENC_NEG_INF = 0x007fffffu;

__device__ __forceinline__ unsigned long long pk2(float x, float y) {
    unsigned long long r;
    asm("mov.b64 %0, {%1, %2};" : "=l"(r) : "f"(x), "f"(y));
    return r;
}
__device__ __forceinline__ void unpk2(unsigned long long v, float& lo, float& hi) {
    asm("mov.b64 {%0, %1}, %2;" : "=f"(lo), "=f"(hi) : "l"(v));
}
__device__ __forceinline__ void fma2(unsigned long long& c, unsigned long long a, unsigned long long b) {
    asm("fma.rn.f32x2 %0, %1, %2, %0;" : "+l"(c) : "l"(a), "l"(b));
}

// ---------------- init ----------------
__global__ void init_kernel() {
    int i0 = blockIdx.x * blockDim.x + threadIdx.x;
    int stride = gridDim.x * blockDim.x;
    for (int i = i0; i < N_; i += stride) { d_cnt_row[i] = 0; d_cnt_col[i] = 0; }
    for (int i = i0; i < G_ * C_; i += stride) d_gmax[i] = ENC_NEG_INF;
}

__global__ void cnt_kernel(const int* __restrict__ row, const int* __restrict__ col) {
    int e = blockIdx.x * blockDim.x + threadIdx.x;
    if (e < E_) {
        atomicAdd(&d_cnt_row[row[e]], 1);
        atomicAdd(&d_cnt_col[col[e]], 1);
    }
}

// single-block exclusive scan (grid of 2: block 0 -> row, block 1 -> col)
__global__ __launch_bounds__(256) void scan_kernel() {
    __shared__ int warpsums[8];
    __shared__ int s_carry;
    int tid = threadIdx.x;
    const int* cnt = (blockIdx.x == 0) ? d_cnt_row : d_cnt_col;
    int* ptr       = (blockIdx.x == 0) ? d_rowptr  : d_colptr;
    if (tid == 0) s_carry = 0;
    __syncthreads();
    for (int base = 0; base < N_; base += 256) {
        int v = (base + tid < N_) ? cnt[base + tid] : 0;
        int x = v;
        #pragma unroll
        for (int o = 1; o < 32; o <<= 1) {
            int y = __shfl_up_sync(0xffffffffu, x, o);
            if ((tid & 31) >= o) x += y;
        }
        if ((tid & 31) == 31) warpsums[tid >> 5] = x;
        __syncthreads();
        if (tid < 8) {
            int w = warpsums[tid];
            #pragma unroll
            for (int o = 1; o < 8; o <<= 1) {
                int y = __shfl_up_sync(0xffu, w, o);
                if (tid >= o) w += y;
            }
            warpsums[tid] = w;
        }
        __syncthreads();
        int prev = (tid >= 32) ? warpsums[(tid >> 5) - 1] : 0;
        if (base + tid < N_) ptr[base + tid] = s_carry + prev + x - v;
        __syncthreads();
        if (tid == 0) s_carry += warpsums[7];
        __syncthreads();
    }
    if (tid == 0) ptr[N_] = s_carry;
}

__global__ void copycur_kernel() {
    int i = blockIdx.x * blockDim.x + threadIdx.x;
    if (i < N_) { d_rowcur[i] = d_rowptr[i]; d_colcur[i] = d_colptr[i]; }
}

__global__ void fill_kernel(const int* __restrict__ row, const int* __restrict__ col) {
    int e = blockIdx.x * blockDim.x + threadIdx.x;
    if (e >= E_) return;
    int j = col[e];
    int p = atomicAdd(&d_rowcur[row[e]], 1);
    d_rowe[p] = e;
    d_rowj[p] = j;
    int q = atomicAdd(&d_colcur[j], 1);
    d_cole[q] = e;
}

// ---------------- SGEMM (unchanged): C = A(MxK) @ B(KxNn) [+bias] ----------------
__global__ __launch_bounds__(256) void sgemm_kernel(
    const float* __restrict__ A, const float* __restrict__ B,
    const float* __restrict__ bias, float* __restrict__ Cm,
    int M, int K, int Nn)
{
    constexpr int BM = 128, BN = 64, BK = 16;
    __shared__ float As[BK][132];
    __shared__ float Bs[BK][BN];

    const int bm = blockIdx.x * BM;
    const int bn = blockIdx.y * BN;
    const int tid = threadIdx.x;
    const int ty = tid >> 4;
    const int tx = tid & 15;

    unsigned long long acc[4][4];
    #pragma unroll
    for (int m = 0; m < 4; m++)
        #pragma unroll
        for (int n = 0; n < 4; n++) acc[m][n] = 0ull;

    for (int k0 = 0; k0 < K; k0 += BK) {
        #pragma unroll
        for (int l = 0; l < 2; l++) {
            int idx = tid + l * 256;
            int r = idx >> 2;
            int kk = (idx & 3) * 4;
            float4 v = make_float4(0.f, 0.f, 0.f, 0.f);
            int gr = bm + r;
            if (gr < M) v = *(const float4*)&A[(size_t)gr * K + k0 + kk];
            As[kk + 0][r] = v.x; As[kk + 1][r] = v.y; As[kk + 2][r] = v.z; As[kk + 3][r] = v.w;
        }
        {
            int kb = tid >> 4;
            int cb = (tid & 15) * 4;
            float4 v = *(const float4*)&B[(size_t)(k0 + kb) * Nn + bn + cb];
            *(float4*)&Bs[kb][cb] = v;
        }
        __syncthreads();

        #pragma unroll
        for (int k = 0; k < BK; k++) {
            ulonglong2 t1 = *(const ulonglong2*)&As[k][ty * 8];
            ulonglong2 t2 = *(const ulonglong2*)&As[k][ty * 8 + 4];
            unsigned long long ap[4] = { t1.x, t1.y, t2.x, t2.y };
            float4 b = *(const float4*)&Bs[k][tx * 4];
            unsigned long long bd[4];
            bd[0] = pk2(b.x, b.x); bd[1] = pk2(b.y, b.y);
            bd[2] = pk2(b.z, b.z); bd[3] = pk2(b.w, b.w);
            #pragma unroll
            for (int m = 0; m < 4; m++)
                #pragma unroll
                for (int n = 0; n < 4; n++)
                    fma2(acc[m][n], ap[m], bd[n]);
        }
        __syncthreads();
    }

    float bv[4] = {0.f, 0.f, 0.f, 0.f};
    if (bias) {
        #pragma unroll
        for (int n = 0; n < 4; n++) bv[n] = bias[bn + tx * 4 + n];
    }
    #pragma unroll
    for (int m = 0; m < 4; m++) {
        float lo[4], hi[4];
        #pragma unroll
        for (int n = 0; n < 4; n++) unpk2(acc[m][n], lo[n], hi[n]);
        int r0 = bm + ty * 8 + 2 * m;
        int r1 = r0 + 1;
        if (r0 < M) {
            float4 o = make_float4(lo[0] + bv[0], lo[1] + bv[1], lo[2] + bv[2], lo[3] + bv[3]);
            *(float4*)&Cm[(size_t)r0 * Nn + bn + tx * 4] = o;
        }
        if (r1 < M) {
            float4 o = make_float4(hi[0] + bv[0], hi[1] + bv[1], hi[2] + bv[2], hi[3] + bv[3]);
            *(float4*)&Cm[(size_t)r1 * Nn + bn + tx * 4] = o;
        }
    }
}

// ---------------- self-loop attr projection: CSR gather mean ----------------
__global__ __launch_bounds__(320) void lep_kernel() {
    int n = blockIdx.x;
    int tid = threadIdx.x;          // 0..319: [0,256) -> lep1, [256,320) -> lep2
    int beg = d_colptr[n], end = d_colptr[n + 1];
    float s = 0.f;
    if (tid < HC_) {
        for (int idx = beg; idx < end; idx++)
            s += d_ep1[(size_t)d_cole[idx] * HC_ + tid];
    } else {
        int c = tid - HC_;
        for (int idx = beg; idx < end; idx++)
            s += d_ep2[(size_t)d_cole[idx] * C_ + c];
    }
    float inv = 1.0f / (float)max(end - beg, 1);
    if (tid < HC_) d_lep1[(size_t)n * HC_ + tid] = s * inv;
    else           d_lep2[(size_t)n * C_ + (tid - HC_)] = s * inv;
}

// ---------------- layer 1 attention: block per node, online softmax ----------------
__global__ __launch_bounds__(256) void att1_kernel(const float* __restrict__ att,
                                                   const float* __restrict__ bias) {
    int i = blockIdx.x;
    int tid = threadIdx.x;          // channel 0..255
    int h = tid >> 6;               // head
    int lane = tid & 31;
    int wid = tid >> 5;
    __shared__ float s_red[2][8];

    float xr_c = d_xr1[(size_t)i * HC_ + tid];
    float att_c = att[tid];

    int beg = d_rowptr[i], end = d_rowptr[i + 1];

    float m = -CUDART_INF_F, den = 0.f, acc = 0.f;

    // prefetch first element (idx = beg); self-loop sits at idx == end
    float xlv, epv;
    if (beg < end) {
        int e = d_rowe[beg], j = d_rowj[beg];
        xlv = d_xl1[(size_t)j * HC_ + tid];
        epv = d_ep1[(size_t)e * HC_ + tid];
    } else {
        xlv = d_xl1[(size_t)i * HC_ + tid];
        epv = d_lep1[(size_t)i * HC_ + tid];
    }

    for (int idx = beg; idx <= end; idx++) {
        float xl_c = xlv, ep_c = epv;
        int nxt = idx + 1;
        if (nxt < end) {
            int e = d_rowe[nxt], j = d_rowj[nxt];
            xlv = d_xl1[(size_t)j * HC_ + tid];
            epv = d_ep1[(size_t)e * HC_ + tid];
        } else if (nxt == end) {
            xlv = d_xl1[(size_t)i * HC_ + tid];
            epv = d_lep1[(size_t)i * HC_ + tid];
        }

        float v = xl_c + xr_c + ep_c;
        v = v > 0.f ? v : 0.2f * v;
        float t = v * att_c;
        #pragma unroll
        for (int o = 1; o < 32; o <<= 1) t += __shfl_xor_sync(0xffffffffu, t, o);
        int buf = idx & 1;
        if (lane == 0) s_red[buf][wid] = t;
        __syncthreads();
        float logit = s_red[buf][2 * h] + s_red[buf][2 * h + 1];

        float mn = fmaxf(m, logit);
        float sc = __expf(m - mn);
        float ex = __expf(logit - mn);
        den = den * sc + ex;
        acc = acc * sc + xl_c * ex;
        m = mn;
    }

    float o = acc / den + bias[tid];
    d_h1[(size_t)i * HC_ + tid] = o > 0.f ? o : 0.01f * o;
}

// ---------------- layer 2 attention: warp per node ----------------
__global__ __launch_bounds__(256) void att2_kernel(const float* __restrict__ att,
                                                   const float* __restrict__ bias) {
    int i = (blockIdx.x * blockDim.x + threadIdx.x) >> 5;
    int lane = threadIdx.x & 31;
    if (i >= N_) return;

    float2 xr = ((const float2*)(d_xr2 + (size_t)i * C_))[lane];
    float2 at = ((const float2*)att)[lane];

    int beg = d_rowptr[i], end = d_rowptr[i + 1];
    float m = -CUDART_INF_F, den = 0.f;
    float2 acc = make_float2(0.f, 0.f);

    float2 xlv, epv;
    if (beg < end) {
        int e = d_rowe[beg], j = d_rowj[beg];
        xlv = ((const float2*)(d_xl2 + (size_t)j * C_))[lane];
        epv = ((const float2*)(d_ep2 + (size_t)e * C_))[lane];
    } else {
        xlv = ((const float2*)(d_xl2 + (size_t)i * C_))[lane];
        epv = ((const float2*)(d_lep2 + (size_t)i * C_))[lane];
    }

    for (int idx = beg; idx <= end; idx++) {
        float2 xl = xlv, e2 = epv;
        int nxt = idx + 1;
        if (nxt < end) {
            int e = d_rowe[nxt], j = d_rowj[nxt];
            xlv = ((const float2*)(d_xl2 + (size_t)j * C_))[lane];
            epv = ((const float2*)(d_ep2 + (size_t)e * C_))[lane];
        } else if (nxt == end) {
            xlv = ((const float2*)(d_xl2 + (size_t)i * C_))[lane];
            epv = ((const float2*)(d_lep2 + (size_t)i * C_))[lane];
        }

        float v0 = xl.x + xr.x + e2.x; v0 = v0 > 0.f ? v0 : 0.2f * v0;
        float v1 = xl.y + xr.y + e2.y; v1 = v1 > 0.f ? v1 : 0.2f * v1;
        float t = v0 * at.x + v1 * at.y;
        #pragma unroll
        for (int o = 1; o < 32; o <<= 1) t += __shfl_xor_sync(0xffffffffu, t, o);

        float mn = fmaxf(m, t);
        float sc = __expf(m - mn);
        float ex = __expf(t - mn);
        den = den * sc + ex;
        acc.x = acc.x * sc + xl.x * ex;
        acc.y = acc.y * sc + xl.y * ex;
        m = mn;
    }

    float2 bv = ((const float2*)bias)[lane];
    float o0 = acc.x / den + bv.x;
    float o1 = acc.y / den + bv.y;
    o0 = o0 > 0.f ? o0 : 0.01f * o0;
    o1 = o1 > 0.f ? o1 : 0.01f * o1;
    ((float2*)(d_h2 + (size_t)i * C_))[lane] = make_float2(o0, o1);
}

// ---------------- global max pool ----------------
__global__ void pool_kernel(const int* __restrict__ batch) {
    int idx = blockIdx.x * blockDim.x + threadIdx.x;
    if (idx >= N_ * C_) return;
    int n = idx >> 6;
    int c = idx & 63;
    atomicMax(&d_gmax[batch[n] * C_ + c], fenc(d_h2[idx]));
}

// ---------------- layernorm + classifier ----------------
__global__ void final_kernel(const float* __restrict__ ln_g, const float* __restrict__ ln_b,
                             const float* __restrict__ clf_W, const float* __restrict__ clf_b,
                             float* __restrict__ out, int out_size) {
    int g = blockIdx.x;
    int tid = threadIdx.x;
    __shared__ float sg[C_];
    __shared__ float sgn[C_];
    __shared__ float s_mu, s_rstd;
    if (tid < C_) sg[tid] = fdec(d_gmax[g * C_ + tid]);
    __syncthreads();
    if (tid == 0) {
        float m = 0.f;
        for (int c = 0; c < C_; c++) m += sg[c];
        m *= (1.0f / C_);
        float v = 0.f;
        for (int c = 0; c < C_; c++) { float d = sg[c] - m; v += d * d; }
        v *= (1.0f / C_);
        s_mu = m;
        s_rstd = rsqrtf(v + 1e-5f);
    }
    __syncthreads();
    if (tid < C_) {
        float gn = (sg[tid] - s_mu) * s_rstd * ln_g[tid] + ln_b[tid];
        sgn[tid] = gn;
        if (out_size >= G_ * NC_ + G_ * C_) out[G_ * NC_ + g * C_ + tid] = gn;
    }
    __syncthreads();
    for (int o = tid; o < NC_; o += blockDim.x) {
        float s = clf_b[o];
        #pragma unroll 8
        for (int c = 0; c < C_; c++) s += sgn[c] * clf_W[c * NC_ + o];
        out[g * NC_ + o] = s;
    }
}

// ---------------- launch ----------------
extern "C" void kernel_launch(void* const* d_in, const int* in_sizes, int n_in,
                              void* d_out, int out_size) {
    const float* x     = (const float*)d_in[0];
    const int*   ei    = (const int*)  d_in[1];
    const float* ea    = (const float*)d_in[2];
    const int*   batch = (const int*)  d_in[3];
    const float* W1l = (const float*)d_in[4];  const float* b1l  = (const float*)d_in[5];
    const float* W1r = (const float*)d_in[6];  const float* b1r  = (const float*)d_in[7];
    const float* W1e = (const float*)d_in[8];  const float* att1 = (const float*)d_in[9];
    const float* bias1 = (const float*)d_in[10];
    const float* W2l = (const float*)d_in[11]; const float* b2l  = (const float*)d_in[12];
    const float* W2r = (const float*)d_in[13]; const float* b2r  = (const float*)d_in[14];
    const float* W2e = (const float*)d_in[15]; const float* att2 = (const float*)d_in[16];
    const float* bias2 = (const float*)d_in[17];
    const float* ln_g = (const float*)d_in[18]; const float* ln_b = (const float*)d_in[19];
    const float* clfW = (const float*)d_in[20]; const float* clfb = (const float*)d_in[21];

    const int* row = ei;
    const int* col = ei + E_;
    float* out = (float*)d_out;

    float *p_xl1, *p_xr1, *p_ep1, *p_ep2, *p_h1, *p_xl2, *p_xr2;
    cudaGetSymbolAddress((void**)&p_xl1, d_xl1);
    cudaGetSymbolAddress((void**)&p_xr1, d_xr1);
    cudaGetSymbolAddress((void**)&p_ep1, d_ep1);
    cudaGetSymbolAddress((void**)&p_ep2, d_ep2);
    cudaGetSymbolAddress((void**)&p_h1,  d_h1);
    cudaGetSymbolAddress((void**)&p_xl2, d_xl2);
    cudaGetSymbolAddress((void**)&p_xr2, d_xr2);

    // CSR build
    init_kernel<<<256, 256>>>();
    cnt_kernel<<<(E_ + 255) / 256, 256>>>(row, col);
    scan_kernel<<<2, 256>>>();
    copycur_kernel<<<(N_ + 255) / 256, 256>>>();
    fill_kernel<<<(E_ + 255) / 256, 256>>>(row, col);

    // GEMMs
    {
        dim3 gE((E_ + 127) / 128, HC_ / 64);
        sgemm_kernel<<<gE, 256>>>(ea, W1e, nullptr, p_ep1, E_, 384, HC_);
        dim3 gE2((E_ + 127) / 128, 1);
        sgemm_kernel<<<gE2, 256>>>(ea, W2e, nullptr, p_ep2, E_, 384, C_);
        dim3 gX((N_ + 127) / 128, HC_ / 64);
        sgemm_kernel<<<gX, 256>>>(x, W1l, b1l, p_xl1, N_, 512, HC_);
        sgemm_kernel<<<gX, 256>>>(x, W1r, b1r, p_xr1, N_, 512, HC_);
    }

    // self-loop attrs (gather by col)
    lep_kernel<<<N_, 320>>>();

    // layer 1 attention (no atomics)
    att1_kernel<<<N_, 256>>>(att1, bias1);

    // layer 2 transforms
    {
        dim3 gH((N_ + 127) / 128, 1);
        sgemm_kernel<<<gH, 256>>>(p_h1, W2l, b2l, p_xl2, N_, HC_, C_);
        sgemm_kernel<<<gH, 256>>>(p_h1, W2r, b2r, p_xr2, N_, HC_, C_);
    }

    // layer 2 attention
    att2_kernel<<<(N_ * 32 + 255) / 256, 256>>>(att2, bias2);

    pool_kernel<<<(N_ * C_ + 255) / 256, 256>>>(batch);
    final_kernel<<<G_, 256>>>(ln_g, ln_b, clfW, clfb, out, out_size);
}

// round 7
// speedup vs baseline: 1.8162x; 1.5645x over previous
#include <cuda_runtime.h>
#include <cuda_bf16.h>
#include <math_constants.h>

typedef unsigned int u32;

// ---------------- problem constants ----------------
constexpr int N_  = 20000;
constexpr int E_  = 200000;
constexpr int H_  = 4;
constexpr int C_  = 64;
constexpr int G_  = 64;
constexpr int NC_ = 751;
constexpr int HC_ = H_ * C_;       // 256

// ---------------- scratch (device globals; no allocation allowed) ----------------
__device__ float    d_xl1[(size_t)N_ * HC_];
__device__ float    d_xr1[(size_t)N_ * HC_];
__device__ float    d_ep1[(size_t)E_ * HC_];
__device__ float    d_ep2[(size_t)E_ * C_];
__device__ float    d_lep1[(size_t)N_ * HC_];
__device__ float    d_lep2[(size_t)N_ * C_];
__device__ float    d_h1[(size_t)N_ * HC_];
__device__ float    d_h2[(size_t)N_ * C_];
__device__ float    d_xl2[(size_t)N_ * C_];
__device__ float    d_xr2[(size_t)N_ * C_];
__device__ unsigned d_gmax[G_ * C_];

// split-bf16 weight buffers: [N rows][K cols] K-major (transposed from input [K][N])
__device__ __nv_bfloat16 d_Bep_hi[320 * 384];
__device__ __nv_bfloat16 d_Bep_lo[320 * 384];
__device__ __nv_bfloat16 d_Bx_hi[512 * 512];
__device__ __nv_bfloat16 d_Bx_lo[512 * 512];
__device__ __nv_bfloat16 d_Bh_hi[128 * 256];
__device__ __nv_bfloat16 d_Bh_lo[128 * 256];

// CSR structures
__device__ int d_cnt_row[N_];
__device__ int d_cnt_col[N_];
__device__ int d_rowptr[N_ + 1];
__device__ int d_colptr[N_ + 1];
__device__ int d_rowcur[N_];
__device__ int d_colcur[N_];
__device__ int d_rowe[E_];
__device__ int d_rowj[E_];
__device__ int d_cole[E_];

// ---------------- helpers ----------------
__device__ __forceinline__ unsigned fenc(float f) {
    unsigned u = __float_as_uint(f);
    return (u & 0x80000000u) ? ~u : (u | 0x80000000u);
}
__device__ __forceinline__ float fdec(unsigned u) {
    u = (u & 0x80000000u) ? (u & 0x7fffffffu) : ~u;
    return __uint_as_float(u);
}
constexpr unsigned ENC_NEG_INF = 0x007fffffu;

__device__ __forceinline__ u32 pack_bf16(float x, float y) {
    unsigned short lo = __bfloat16_as_ushort(__float2bfloat16(x));
    unsigned short hi = __bfloat16_as_ushort(__float2bfloat16(y));
    return (u32)lo | ((u32)hi << 16);
}
__device__ __forceinline__ float bf_res(float x) {
    return x - __bfloat162float(__float2bfloat16(x));
}

__device__ __forceinline__ void mma16816(float& c0, float& c1, float& c2, float& c3,
                                         u32 a0, u32 a1, u32 a2, u32 a3,
                                         u32 b0, u32 b1) {
    asm volatile(
        "mma.sync.aligned.m16n8k16.row.col.f32.bf16.bf16.f32 "
        "{%0,%1,%2,%3}, {%4,%5,%6,%7}, {%8,%9}, {%0,%1,%2,%3};"
        : "+f"(c0), "+f"(c1), "+f"(c2), "+f"(c3)
        : "r"(a0), "r"(a1), "r"(a2), "r"(a3), "r"(b0), "r"(b1));
}

// ---------------- weight prep: transpose + bf16 split ----------------
__global__ void prep_weights(const float* __restrict__ W1e, const float* __restrict__ W2e,
                             const float* __restrict__ W1l, const float* __restrict__ W1r,
                             const float* __restrict__ W2l, const float* __restrict__ W2r) {
    int idx = blockIdx.x * blockDim.x + threadIdx.x;
    if (idx < 320 * 384) {
        int n = idx / 384;
        int k = idx % 384;
        float v = (n < 256) ? W1e[k * 256 + n] : W2e[k * 64 + (n - 256)];
        __nv_bfloat16 h = __float2bfloat16(v);
        d_Bep_hi[idx] = h;
        d_Bep_lo[idx] = __float2bfloat16(v - __bfloat162float(h));
    }
    if (idx < 512 * 512) {
        int n = idx >> 9;
        int k = idx & 511;
        float v = (n < 256) ? W1l[k * 256 + n] : W1r[k * 256 + (n - 256)];
        __nv_bfloat16 h = __float2bfloat16(v);
        d_Bx_hi[idx] = h;
        d_Bx_lo[idx] = __float2bfloat16(v - __bfloat162float(h));
    }
    if (idx < 128 * 256) {
        int n = idx >> 8;
        int k = idx & 255;
        float v = (n < 64) ? W2l[k * 64 + n] : W2r[k * 64 + (n - 64)];
        __nv_bfloat16 h = __float2bfloat16(v);
        d_Bh_hi[idx] = h;
        d_Bh_lo[idx] = __float2bfloat16(v - __bfloat162float(h));
    }
}

// ---------------- mma.sync split-bf16 GEMM ----------------
// C[M, N1+N2]: cols [0,N1) -> out1 (+bias1), [N1,N1+N2) -> out2 (+bias2).
// B buffers: [N1+N2 rows][K] bf16 hi/lo, K contiguous (PTX .col layout).
// 3-term split via physical K concat: smem rows hold [hi(64) | lo(64) | hi(64)] for A
// and [hi | hi | lo] for B, so mma over 192 cols computes Ahi*Bhi + Alo*Bhi + Ahi*Blo.
// Block tile 128x128, warp tile 32x64 (warps 4M x 2N). Row stride 400B => conflict-free.
__global__ __launch_bounds__(256) void mma_gemm(
    const float* __restrict__ A, int K, int M,
    const __nv_bfloat16* __restrict__ Bhi, const __nv_bfloat16* __restrict__ Blo,
    float* __restrict__ out1, float* __restrict__ out2,
    const float* __restrict__ bias1, const float* __restrict__ bias2,
    int N1, int N2)
{
    extern __shared__ char smem[];
    char* Asm = smem;            // 128 rows * 400B = 51200
    char* Bsm = smem + 51200;    // 128 rows * 400B = 51200

    const int tid = threadIdx.x;
    const int wid = tid >> 5;
    const int lane = tid & 31;
    const int m0 = blockIdx.x * 128;
    const int n0 = blockIdx.y * 128;
    const int NT = N1 + N2;
    const int warpRow = (wid & 3) * 32;
    const int warpCol = (wid >> 2) * 64;

    float acc[2][8][4];
    #pragma unroll
    for (int i = 0; i < 2; i++)
        #pragma unroll
        for (int j = 0; j < 8; j++)
            #pragma unroll
            for (int q = 0; q < 4; q++)
                acc[i][j][q] = 0.f;

    for (int k0 = 0; k0 < K; k0 += 64) {
        __syncthreads();
        // ---- A chunk: 128 rows x 64 fp32 -> bf16 hi/lo concat ----
        #pragma unroll
        for (int it = 0; it < 8; it++) {
            int idx = tid + it * 256;
            int r = idx >> 4;
            int q = idx & 15;
            float4 v = make_float4(0.f, 0.f, 0.f, 0.f);
            if (m0 + r < M) v = *(const float4*)(A + (size_t)(m0 + r) * K + k0 + q * 4);
            u32 h0 = pack_bf16(v.x, v.y);
            u32 h1 = pack_bf16(v.z, v.w);
            u32 l0 = pack_bf16(bf_res(v.x), bf_res(v.y));
            u32 l1 = pack_bf16(bf_res(v.z), bf_res(v.w));
            char* rowp = Asm + r * 400 + q * 8;
            *(uint2*)(rowp)       = make_uint2(h0, h1);
            *(uint2*)(rowp + 128) = make_uint2(l0, l1);
            *(uint2*)(rowp + 256) = make_uint2(h0, h1);
        }
        // ---- B chunk: 128 rows x 64 bf16 hi/lo concat [hi|hi|lo] ----
        #pragma unroll
        for (int it = 0; it < 4; it++) {
            int idx = tid + it * 256;
            int n = idx >> 3;
            int q = idx & 7;
            uint4 vh = make_uint4(0u, 0u, 0u, 0u);
            uint4 vl = vh;
            if (n0 + n < NT) {
                vh = *(const uint4*)(Bhi + (size_t)(n0 + n) * K + k0 + q * 8);
                vl = *(const uint4*)(Blo + (size_t)(n0 + n) * K + k0 + q * 8);
            }
            char* rowp = Bsm + n * 400 + q * 16;
            *(uint4*)(rowp)       = vh;
            *(uint4*)(rowp + 128) = vh;
            *(uint4*)(rowp + 256) = vl;
        }
        __syncthreads();

        // ---- mma over 192 concat columns ----
        #pragma unroll
        for (int kk = 0; kk < 192; kk += 16) {
            u32 a[2][4];
            #pragma unroll
            for (int mt = 0; mt < 2; mt++) {
                const char* ap = Asm + (warpRow + mt * 16 + (lane >> 2)) * 400
                               + (kk + (lane & 3) * 2) * 2;
                a[mt][0] = *(const u32*)(ap);
                a[mt][1] = *(const u32*)(ap + 8 * 400);
                a[mt][2] = *(const u32*)(ap + 16);
                a[mt][3] = *(const u32*)(ap + 8 * 400 + 16);
            }
            u32 b[8][2];
            #pragma unroll
            for (int nt = 0; nt < 8; nt++) {
                const char* bp = Bsm + (warpCol + nt * 8 + (lane >> 2)) * 400
                               + (kk + (lane & 3) * 2) * 2;
                b[nt][0] = *(const u32*)(bp);
                b[nt][1] = *(const u32*)(bp + 16);
            }
            #pragma unroll
            for (int mt = 0; mt < 2; mt++)
                #pragma unroll
                for (int nt = 0; nt < 8; nt++)
                    mma16816(acc[mt][nt][0], acc[mt][nt][1], acc[mt][nt][2], acc[mt][nt][3],
                             a[mt][0], a[mt][1], a[mt][2], a[mt][3], b[nt][0], b[nt][1]);
        }
    }

    // ---- epilogue ----
    #pragma unroll
    for (int mt = 0; mt < 2; mt++) {
        int r0 = m0 + warpRow + mt * 16 + (lane >> 2);
        #pragma unroll
        for (int nt = 0; nt < 8; nt++) {
            int gc = n0 + warpCol + nt * 8 + (lane & 3) * 2;
            if (gc >= NT) continue;
            float* o;
            const float* bs;
            int Nn, cc;
            if (gc < N1) { o = out1; bs = bias1; Nn = N1; cc = gc; }
            else         { o = out2; bs = bias2; Nn = N2; cc = gc - N1; }
            float bv0 = 0.f, bv1 = 0.f;
            if (bs != 0) { bv0 = bs[cc]; bv1 = bs[cc + 1]; }
            if (r0 < M) {
                float2 w = make_float2(acc[mt][nt][0] + bv0, acc[mt][nt][1] + bv1);
                *(float2*)(o + (size_t)r0 * Nn + cc) = w;
            }
            if (r0 + 8 < M) {
                float2 w = make_float2(acc[mt][nt][2] + bv0, acc[mt][nt][3] + bv1);
                *(float2*)(o + (size_t)(r0 + 8) * Nn + cc) = w;
            }
        }
    }
}

// ---------------- init ----------------
__global__ void init_kernel() {
    int i0 = blockIdx.x * blockDim.x + threadIdx.x;
    int stride = gridDim.x * blockDim.x;
    for (int i = i0; i < N_; i += stride) {
        d_cnt_row[i] = 0;
        d_cnt_col[i] = 0;
    }
    for (int i = i0; i < G_ * C_; i += stride) d_gmax[i] = ENC_NEG_INF;
}

__global__ void cnt_kernel(const int* __restrict__ row, const int* __restrict__ col) {
    int e = blockIdx.x * blockDim.x + threadIdx.x;
    if (e < E_) {
        atomicAdd(&d_cnt_row[row[e]], 1);
        atomicAdd(&d_cnt_col[col[e]], 1);
    }
}

__global__ __launch_bounds__(256) void scan_kernel() {
    __shared__ int warpsums[8];
    __shared__ int s_carry;
    int tid = threadIdx.x;
    const int* cnt = (blockIdx.x == 0) ? d_cnt_row : d_cnt_col;
    int* ptr       = (blockIdx.x == 0) ? d_rowptr  : d_colptr;
    if (tid == 0) s_carry = 0;
    __syncthreads();
    for (int base = 0; base < N_; base += 256) {
        int v = (base + tid < N_) ? cnt[base + tid] : 0;
        int x = v;
        #pragma unroll
        for (int o = 1; o < 32; o <<= 1) {
            int y = __shfl_up_sync(0xffffffffu, x, o);
            if ((tid & 31) >= o) x += y;
        }
        if ((tid & 31) == 31) warpsums[tid >> 5] = x;
        __syncthreads();
        if (tid < 8) {
            int w = warpsums[tid];
            #pragma unroll
            for (int o = 1; o < 8; o <<= 1) {
                int y = __shfl_up_sync(0xffu, w, o);
                if (tid >= o) w += y;
            }
            warpsums[tid] = w;
        }
        __syncthreads();
        int prev = (tid >= 32) ? warpsums[(tid >> 5) - 1] : 0;
        if (base + tid < N_) ptr[base + tid] = s_carry + prev + x - v;
        __syncthreads();
        if (tid == 0) s_carry += warpsums[7];
        __syncthreads();
    }
    if (tid == 0) ptr[N_] = s_carry;
}

__global__ void copycur_kernel() {
    int i = blockIdx.x * blockDim.x + threadIdx.x;
    if (i < N_) {
        d_rowcur[i] = d_rowptr[i];
        d_colcur[i] = d_colptr[i];
    }
}

__global__ void fill_kernel(const int* __restrict__ row, const int* __restrict__ col) {
    int e = blockIdx.x * blockDim.x + threadIdx.x;
    if (e >= E_) return;
    int j = col[e];
    int p = atomicAdd(&d_rowcur[row[e]], 1);
    d_rowe[p] = e;
    d_rowj[p] = j;
    int q = atomicAdd(&d_colcur[j], 1);
    d_cole[q] = e;
}

// ---------------- self-loop attr projection: CSR gather mean ----------------
__global__ __launch_bounds__(320) void lep_kernel() {
    int n = blockIdx.x;
    int tid = threadIdx.x;
    int beg = d_colptr[n];
    int end = d_colptr[n + 1];
    float s = 0.f;
    if (tid < HC_) {
        for (int idx = beg; idx < end; idx++)
            s += d_ep1[(size_t)d_cole[idx] * HC_ + tid];
    } else {
        int c = tid - HC_;
        for (int idx = beg; idx < end; idx++)
            s += d_ep2[(size_t)d_cole[idx] * C_ + c];
    }
    float inv = 1.0f / (float)max(end - beg, 1);
    if (tid < HC_) d_lep1[(size_t)n * HC_ + tid] = s * inv;
    else           d_lep2[(size_t)n * C_ + (tid - HC_)] = s * inv;
}

// ---------------- layer 1 attention: block per node, online softmax ----------------
__global__ __launch_bounds__(256) void att1_kernel(const float* __restrict__ att,
                                                   const float* __restrict__ bias) {
    int i = blockIdx.x;
    int tid = threadIdx.x;
    int h = tid >> 6;
    int lane = tid & 31;
    int wid = tid >> 5;
    __shared__ float s_red[2][8];

    float xr_c = d_xr1[(size_t)i * HC_ + tid];
    float att_c = att[tid];

    int beg = d_rowptr[i];
    int end = d_rowptr[i + 1];

    float m = -CUDART_INF_F;
    float den = 0.f;
    float acc = 0.f;

    float xlv, epv;
    if (beg < end) {
        int e = d_rowe[beg];
        int j = d_rowj[beg];
        xlv = d_xl1[(size_t)j * HC_ + tid];
        epv = d_ep1[(size_t)e * HC_ + tid];
    } else {
        xlv = d_xl1[(size_t)i * HC_ + tid];
        epv = d_lep1[(size_t)i * HC_ + tid];
    }

    for (int idx = beg; idx <= end; idx++) {
        float xl_c = xlv;
        float ep_c = epv;
        int nxt = idx + 1;
        if (nxt < end) {
            int e = d_rowe[nxt];
            int j = d_rowj[nxt];
            xlv = d_xl1[(size_t)j * HC_ + tid];
            epv = d_ep1[(size_t)e * HC_ + tid];
        } else if (nxt == end) {
            xlv = d_xl1[(size_t)i * HC_ + tid];
            epv = d_lep1[(size_t)i * HC_ + tid];
        }

        float v = xl_c + xr_c + ep_c;
        v = v > 0.f ? v : 0.2f * v;
        float t = v * att_c;
        #pragma unroll
        for (int o = 1; o < 32; o <<= 1) t += __shfl_xor_sync(0xffffffffu, t, o);
        int buf = idx & 1;
        if (lane == 0) s_red[buf][wid] = t;
        __syncthreads();
        float logit = s_red[buf][2 * h] + s_red[buf][2 * h + 1];

        float mn = fmaxf(m, logit);
        float sc = __expf(m - mn);
        float ex = __expf(logit - mn);
        den = den * sc + ex;
        acc = acc * sc + xl_c * ex;
        m = mn;
    }

    float outv = acc / den + bias[tid];
    d_h1[(size_t)i * HC_ + tid] = outv > 0.f ? outv : 0.01f * outv;
}

// ---------------- layer 2 attention: warp per node ----------------
__global__ __launch_bounds__(256) void att2_kernel(const float* __restrict__ att,
                                                   const float* __restrict__ bias) {
    int i = (blockIdx.x * blockDim.x + threadIdx.x) >> 5;
    int lane = threadIdx.x & 31;
    if (i >= N_) return;

    float2 xr = ((const float2*)(d_xr2 + (size_t)i * C_))[lane];
    float2 at = ((const float2*)att)[lane];

    int beg = d_rowptr[i];
    int end = d_rowptr[i + 1];
    float m = -CUDART_INF_F;
    float den = 0.f;
    float accx = 0.f;
    float accy = 0.f;

    float2 xlv, epv;
    if (beg < end) {
        int e = d_rowe[beg];
        int j = d_rowj[beg];
        xlv = ((const float2*)(d_xl2 + (size_t)j * C_))[lane];
        epv = ((const float2*)(d_ep2 + (size_t)e * C_))[lane];
    } else {
        xlv = ((const float2*)(d_xl2 + (size_t)i * C_))[lane];
        epv = ((const float2*)(d_lep2 + (size_t)i * C_))[lane];
    }

    for (int idx = beg; idx <= end; idx++) {
        float2 xl = xlv;
        float2 e2 = epv;
        int nxt = idx + 1;
        if (nxt < end) {
            int e = d_rowe[nxt];
            int j = d_rowj[nxt];
            xlv = ((const float2*)(d_xl2 + (size_t)j * C_))[lane];
            epv = ((const float2*)(d_ep2 + (size_t)e * C_))[lane];
        } else if (nxt == end) {
            xlv = ((const float2*)(d_xl2 + (size_t)i * C_))[lane];
            epv = ((const float2*)(d_lep2 + (size_t)i * C_))[lane];
        }

        float v0 = xl.x + xr.x + e2.x;
        v0 = v0 > 0.f ? v0 : 0.2f * v0;
        float v1 = xl.y + xr.y + e2.y;
        v1 = v1 > 0.f ? v1 : 0.2f * v1;
        float t = v0 * at.x + v1 * at.y;
        #pragma unroll
        for (int o = 1; o < 32; o <<= 1) t += __shfl_xor_sync(0xffffffffu, t, o);

        float mn = fmaxf(m, t);
        float sc = __expf(m - mn);
        float ex = __expf(t - mn);
        den = den * sc + ex;
        accx = accx * sc + xl.x * ex;
        accy = accy * sc + xl.y * ex;
        m = mn;
    }

    float2 bv = ((const float2*)bias)[lane];
    float o0 = accx / den + bv.x;
    float o1 = accy / den + bv.y;
    o0 = o0 > 0.f ? o0 : 0.01f * o0;
    o1 = o1 > 0.f ? o1 : 0.01f * o1;
    ((float2*)(d_h2 + (size_t)i * C_))[lane] = make_float2(o0, o1);
}

// ---------------- global max pool ----------------
__global__ void pool_kernel(const int* __restrict__ batch) {
    int idx = blockIdx.x * blockDim.x + threadIdx.x;
    if (idx >= N_ * C_) return;
    int n = idx >> 6;
    int c = idx & 63;
    atomicMax(&d_gmax[batch[n] * C_ + c], fenc(d_h2[idx]));
}

// ---------------- layernorm + classifier ----------------
__global__ void final_kernel(const float* __restrict__ ln_g, const float* __restrict__ ln_b,
                             const float* __restrict__ clf_W, const float* __restrict__ clf_b,
                             float* __restrict__ out, int out_size) {
    int g = blockIdx.x;
    int tid = threadIdx.x;
    __shared__ float sg[C_];
    __shared__ float sgn[C_];
    __shared__ float s_mu, s_rstd;
    if (tid < C_) sg[tid] = fdec(d_gmax[g * C_ + tid]);
    __syncthreads();
    if (tid == 0) {
        float m = 0.f;
        for (int c = 0; c < C_; c++) m += sg[c];
        m *= (1.0f / C_);
        float v = 0.f;
        for (int c = 0; c < C_; c++) {
            float dd = sg[c] - m;
            v += dd * dd;
        }
        v *= (1.0f / C_);
        s_mu = m;
        s_rstd = rsqrtf(v + 1e-5f);
    }
    __syncthreads();
    if (tid < C_) {
        float gn = (sg[tid] - s_mu) * s_rstd * ln_g[tid] + ln_b[tid];
        sgn[tid] = gn;
        if (out_size >= G_ * NC_ + G_ * C_) out[G_ * NC_ + g * C_ + tid] = gn;
    }
    __syncthreads();
    for (int o = tid; o < NC_; o += blockDim.x) {
        float s = clf_b[o];
        #pragma unroll 8
        for (int c = 0; c < C_; c++) s += sgn[c] * clf_W[c * NC_ + o];
        out[g * NC_ + o] = s;
    }
}

// ---------------- launch ----------------
extern "C" void kernel_launch(void* const* d_in, const int* in_sizes, int n_in,
                              void* d_out, int out_size) {
    const float* x     = (const float*)d_in[0];
    const int*   ei    = (const int*)  d_in[1];
    const float* ea    = (const float*)d_in[2];
    const int*   batch = (const int*)  d_in[3];
    const float* W1l = (const float*)d_in[4];
    const float* b1l  = (const float*)d_in[5];
    const float* W1r = (const float*)d_in[6];
    const float* b1r  = (const float*)d_in[7];
    const float* W1e = (const float*)d_in[8];
    const float* att1 = (const float*)d_in[9];
    const float* bias1 = (const float*)d_in[10];
    const float* W2l = (const float*)d_in[11];
    const float* b2l  = (const float*)d_in[12];
    const float* W2r = (const float*)d_in[13];
    const float* b2r  = (const float*)d_in[14];
    const float* W2e = (const float*)d_in[15];
    const float* att2 = (const float*)d_in[16];
    const float* bias2 = (const float*)d_in[17];
    const float* ln_g = (const float*)d_in[18];
    const float* ln_b = (const float*)d_in[19];
    const float* clfW = (const float*)d_in[20];
    const float* clfb = (const float*)d_in[21];

    const int* row = ei;
    const int* col = ei + E_;
    float* out = (float*)d_out;

    float *p_xl1, *p_xr1, *p_ep1, *p_ep2, *p_h1, *p_xl2, *p_xr2;
    cudaGetSymbolAddress((void**)&p_xl1, d_xl1);
    cudaGetSymbolAddress((void**)&p_xr1, d_xr1);
    cudaGetSymbolAddress((void**)&p_ep1, d_ep1);
    cudaGetSymbolAddress((void**)&p_ep2, d_ep2);
    cudaGetSymbolAddress((void**)&p_h1,  d_h1);
    cudaGetSymbolAddress((void**)&p_xl2, d_xl2);
    cudaGetSymbolAddress((void**)&p_xr2, d_xr2);
    __nv_bfloat16 *pBep_hi, *pBep_lo, *pBx_hi, *pBx_lo, *pBh_hi, *pBh_lo;
    cudaGetSymbolAddress((void**)&pBep_hi, d_Bep_hi);
    cudaGetSymbolAddress((void**)&pBep_lo, d_Bep_lo);
    cudaGetSymbolAddress((void**)&pBx_hi,  d_Bx_hi);
    cudaGetSymbolAddress((void**)&pBx_lo,  d_Bx_lo);
    cudaGetSymbolAddress((void**)&pBh_hi,  d_Bh_hi);
    cudaGetSymbolAddress((void**)&pBh_lo,  d_Bh_lo);

    const int SMEM_MMA = 102400;
    cudaFuncSetAttribute(mma_gemm, cudaFuncAttributeMaxDynamicSharedMemorySize, SMEM_MMA);

    // CSR build
    init_kernel<<<256, 256>>>();
    cnt_kernel<<<(E_ + 255) / 256, 256>>>(row, col);
    scan_kernel<<<2, 256>>>();
    copycur_kernel<<<(N_ + 255) / 256, 256>>>();
    fill_kernel<<<(E_ + 255) / 256, 256>>>(row, col);

    // weight prep
    prep_weights<<<(512 * 512 + 255) / 256, 256>>>(W1e, W2e, W1l, W1r, W2l, W2r);

    // GEMMs on tensor cores (mma.sync / HMMA)
    mma_gemm<<<dim3((E_ + 127) / 128, 3), 256, SMEM_MMA>>>(
        ea, 384, E_, pBep_hi, pBep_lo, p_ep1, p_ep2, (const float*)0, (const float*)0, 256, 64);
    mma_gemm<<<dim3((N_ + 127) / 128, 4), 256, SMEM_MMA>>>(
        x, 512, N_, pBx_hi, pBx_lo, p_xl1, p_xr1, b1l, b1r, 256, 256);

    // self-loop attrs (gather by col)
    lep_kernel<<<N_, 320>>>();

    // layer 1 attention
    att1_kernel<<<N_, 256>>>(att1, bias1);

    // layer 2 transforms
    mma_gemm<<<dim3((N_ + 127) / 128, 1), 256, SMEM_MMA>>>(
        p_h1, 256, N_, pBh_hi, pBh_lo, p_xl2, p_xr2, b2l, b2r, 64, 64);

    // layer 2 attention
    att2_kernel<<<(N_ * 32 + 255) / 256, 256>>>(att2, bias2);

    pool_kernel<<<(N_ * C_ + 255) / 256, 256>>>(batch);
    final_kernel<<<G_, 256>>>(ln_g, ln_b, clfW, clfb, out, out_size);
}